// round 14
// baseline (speedup 1.0000x reference)
#include <cuda_runtime.h>
#include <cuda.h>
#include <cstdint>

// Problem dims (fixed)
#define NB   256
#define LL   2048
#define QK   512
#define HH   128

#define TILE_ROWS 128
#define SPLITS    16                        // per batch
#define NCTAS     2048                      // each CTA: 2 tiles = 256 rows
#define THREADS   256
#define NSTAGE    3
#define NCH       32                        // 2 tiles x 16 K32-chunks

#define A_STAGE_BYTES 16384                 // 128 rows x 128B fp32 (K=32)
#define B_STAGE_BYTES 16384
#define STAGE_TX      (A_STAGE_BYTES + B_STAGE_BYTES)

// smem byte offsets
#define SM_A     0                          // 3 stages
#define SM_B     (3 * A_STAGE_BYTES)        // 49152, 3 stages
#define SM_QS    (SM_B + 3 * B_STAGE_BYTES) // 98304
#define SM_VAS   (SM_QS + 512)              // 98816
#define SM_ES    (SM_VAS + 512)             // 99328: 4 x 128 floats (reused per tile)
#define SM_PS0   (SM_ES + 2048)             // 101376
#define SM_PS1   (SM_PS0 + 512)             // 101888
#define SM_RED   (SM_PS1 + 512)             // 102400
#define SM_CST   (SM_RED + 128)             // 102528: 1 partial ctx slice
#define SM_MBAR  (SM_CST + 2048)            // 104576: full[3] + empty[3]
#define SM_TOTAL (SM_MBAR + 64)             // 104640 = 102.2 KB -> 2 CTAs/SM

// ---------------- device scratch ----------------
__device__ float g_q[NB * HH];
__device__ float g_p[NB * LL];
__device__ float g_pz[NB * SPLITS];
__device__ float g_pc[(size_t)NB * SPLITS * QK];
__device__ int   g_cnt[NB];                 // zero-init; self-resetting

// ---------------- helpers ----------------
__device__ __forceinline__ void mbar_init(uint32_t a, uint32_t cnt) {
    asm volatile("mbarrier.init.shared.b64 [%0], %1;" :: "r"(a), "r"(cnt) : "memory");
}
__device__ __forceinline__ void mbar_expect_tx(uint32_t a, uint32_t bytes) {
    asm volatile("mbarrier.arrive.expect_tx.shared.b64 _, [%0], %1;" :: "r"(a), "r"(bytes) : "memory");
}
__device__ __forceinline__ void mbar_arrive(uint32_t a) {
    asm volatile("mbarrier.arrive.shared.b64 _, [%0];" :: "r"(a) : "memory");
}
__device__ __forceinline__ void mbar_wait(uint32_t a, uint32_t par) {
    asm volatile(
        "{\n\t.reg .pred P1;\n"
        "WAIT_LOOP_%=:\n\t"
        "mbarrier.try_wait.parity.acquire.cta.shared::cta.b64 P1, [%0], %1, 0x989680;\n\t"
        "@P1 bra.uni WAIT_DONE_%=;\n\t"
        "bra.uni WAIT_LOOP_%=;\n"
        "WAIT_DONE_%=:\n\t}"
        :: "r"(a), "r"(par) : "memory");
}
__device__ __forceinline__ void tma2d(uint32_t dst, const CUtensorMap* m, int x, int y, uint32_t bar) {
    asm volatile(
        "cp.async.bulk.tensor.2d.shared::cta.global.tile.mbarrier::complete_tx::bytes "
        "[%0], [%1, {%2, %3}], [%4];"
        :: "r"(dst), "l"(m), "r"(x), "r"(y), "r"(bar) : "memory");
}
__device__ __forceinline__ void mma_tf32(float* c, const uint32_t* a, const uint32_t* b) {
    asm volatile(
        "mma.sync.aligned.m16n8k8.row.col.f32.tf32.tf32.f32 "
        "{%0,%1,%2,%3},{%4,%5,%6,%7},{%8,%9},{%0,%1,%2,%3};"
        : "+f"(c[0]), "+f"(c[1]), "+f"(c[2]), "+f"(c[3])
        : "r"(a[0]), "r"(a[1]), "r"(a[2]), "r"(a[3]), "r"(b[0]), "r"(b[1]));
}
__device__ __forceinline__ void ldsm_x4(uint32_t& r0, uint32_t& r1, uint32_t& r2, uint32_t& r3,
                                        uint32_t addr) {
    asm volatile("ldmatrix.sync.aligned.m8n8.x4.shared.b16 {%0,%1,%2,%3}, [%4];"
                 : "=r"(r0), "=r"(r1), "=r"(r2), "=r"(r3) : "r"(addr));
}
__device__ __forceinline__ float tanh_fast(float x) {
    float y; asm("tanh.approx.f32 %0, %1;" : "=f"(y) : "f"(x)); return y;
}

// ---------------- kernel 0: q projection (coalesced, warp-per-rows) ----------------
__global__ void __launch_bounds__(512)
k_qproj(const float* __restrict__ last_hidden, const float* __restrict__ Wa) {
    const int n    = blockIdx.x;
    const int warp = threadIdx.x >> 5;
    const int lane = threadIdx.x & 31;

    const float4* x4 = reinterpret_cast<const float4*>(last_hidden + (size_t)n * QK);
    float4 xv[4];
#pragma unroll
    for (int k = 0; k < 4; ++k) xv[k] = x4[lane + k * 32];

#pragma unroll
    for (int rr = 0; rr < 8; ++rr) {
        const int h = warp * 8 + rr;
        const float4* w4 = reinterpret_cast<const float4*>(Wa + (size_t)h * QK);
        float a = 0.f;
#pragma unroll
        for (int k = 0; k < 4; ++k) {
            float4 w = w4[lane + k * 32];
            a += w.x * xv[k].x + w.y * xv[k].y + w.z * xv[k].z + w.w * xv[k].w;
        }
#pragma unroll
        for (int o = 16; o > 0; o >>= 1) a += __shfl_xor_sync(0xffffffffu, a, o);
        if (lane == 0) g_q[n * HH + h] = a;
    }
}

// ---------------- kernel 1: persistent 2-tile, uniform interleaved tail ----------------
__global__ void __launch_bounds__(THREADS, 2)
k_fused(const __grid_constant__ CUtensorMap tmA,   // X tiles, SW128
        const __grid_constant__ CUtensorMap tmB,   // Ua tiles, SW128
        const float* __restrict__ X,               // (NB,LL,QK) for context re-read
        const float* __restrict__ va,              // (1,HH)
        float* __restrict__ out) {
    extern __shared__ __align__(1024) char sm[];
    const uint32_t su = (uint32_t)__cvta_generic_to_shared(sm);
    float* qs  = reinterpret_cast<float*>(sm + SM_QS);
    float* vas = reinterpret_cast<float*>(sm + SM_VAS);
    float* es  = reinterpret_cast<float*>(sm + SM_ES);
    float* ps0 = reinterpret_cast<float*>(sm + SM_PS0);
    float* ps1 = reinterpret_cast<float*>(sm + SM_PS1);
    float* red = reinterpret_cast<float*>(sm + SM_RED);
    float* cst = reinterpret_cast<float*>(sm + SM_CST);
    __shared__ int s_last;

    const int tid  = threadIdx.x;
    const int bx   = blockIdx.x;
    const int rowA = bx * 256;                 // tile0 rows [rowA, rowA+128)
    const int n    = bx >> 3;                  // batch
    const int sx0  = bx * 2;                   // global split index of tile0

    const int warp = tid >> 5;
    const int lane = tid & 31;
    const int wr = warp >> 2;          // 0..1 : 64-row strip
    const int wc = warp & 3;           // 0..3 : 32-col strip
    const int g  = lane >> 2;
    const int t  = lane & 3;

    // ldmatrix lane addressing (16B segs, SW128-swizzled 128B rows)
    const int swz   = (lane & 7) << 4;
    const int rowAa = lane & 15;
    const int hiA   = (lane >> 4) << 4;
    const int rowBb = (lane & 7) + ((lane >> 4) << 3);
    const int hiB   = ((lane >> 3) & 1) << 4;

    const uint32_t mbf = su + SM_MBAR;        // full[s] at +s*8
    const uint32_t mbe = su + SM_MBAR + 24;   // empty[s] at +s*8

    if (tid == 0) {
#pragma unroll
        for (int s = 0; s < NSTAGE; ++s) {
            mbar_init(mbf + s * 8, 1);
            mbar_init(mbe + s * 8, 8);
        }
    }
    if (tid < HH) {
        vas[tid] = va[tid];
        qs[tid]  = g_q[n * HH + tid];
    }
    __syncthreads();

    // prologue: chunks 0,1 in flight
    if (tid == 0) {
        mbar_expect_tx(mbf + 0, STAGE_TX);
        tma2d(su + SM_A, &tmA, 0, rowA, mbf + 0);
        tma2d(su + SM_B, &tmB, 0, 0, mbf + 0);
        mbar_expect_tx(mbf + 8, STAGE_TX);
        tma2d(su + SM_A + A_STAGE_BYTES, &tmA, 32, rowA, mbf + 8);
        tma2d(su + SM_B + B_STAGE_BYTES, &tmB, 32, 0, mbf + 8);
    }

    float acc[4][4][4];
#pragma unroll
    for (int m = 0; m < 4; ++m)
#pragma unroll
        for (int j = 0; j < 4; ++j)
#pragma unroll
            for (int c = 0; c < 4; ++c) acc[m][j][c] = 0.f;

    const uint32_t a_tile_off = (uint32_t)((wr * 64 + rowAa) * 128);
    const uint32_t b_tile_off = (uint32_t)((wc * 32 + rowBb) * 128);

    // deferred tile0-context accumulator (per thread: 4 cols, 4 rows/slice)
    float4 ctx0 = make_float4(0.f, 0.f, 0.f, 0.f);
    const int c4 = (tid & 127) * 4;
    const int rh = tid >> 7;                  // 0/1 row-subgroup

    // ---- 32-chunk mainloop across both tiles ----
#pragma unroll 1
    for (int kc = 0; kc < NCH; ++kc) {
        const int s = kc % NSTAGE;
        const int phase = (kc / NSTAGE) & 1;

        // producer: chunk kc+2
        if (tid == 0 && kc + 2 < NCH) {
            const int c  = kc + 2;
            const int ns = c % NSTAGE;
            if (c >= NSTAGE)
                mbar_wait(mbe + ns * 8, (uint32_t)(((c - NSTAGE) / NSTAGE) & 1));
            mbar_expect_tx(mbf + ns * 8, STAGE_TX);
            tma2d(su + SM_A + ns * A_STAGE_BYTES, &tmA, (c & 15) * 32,
                  rowA + (c >> 4) * TILE_ROWS, mbf + ns * 8);
            tma2d(su + SM_B + ns * B_STAGE_BYTES, &tmB, (c & 15) * 32, 0, mbf + ns * 8);
        }

        mbar_wait(mbf + s * 8, (uint32_t)phase);

        const uint32_t ab = su + SM_A + s * A_STAGE_BYTES + a_tile_off;
        const uint32_t bb = su + SM_B + s * B_STAGE_BYTES + b_tile_off;

#pragma unroll
        for (int ks = 0; ks < 4; ++ks) {
            const uint32_t colA = (uint32_t)((ks * 32 + hiA) ^ swz);
            const uint32_t colB = (uint32_t)((ks * 32 + hiB) ^ swz);

            uint32_t bu[4][2];
#pragma unroll
            for (int jj = 0; jj < 2; ++jj) {
                ldsm_x4(bu[2*jj][0], bu[2*jj][1], bu[2*jj+1][0], bu[2*jj+1][1],
                        bb + (uint32_t)(jj * 16 * 128) + colB);
            }
#pragma unroll
            for (int m = 0; m < 4; ++m) {
                uint32_t au[4];
                ldsm_x4(au[0], au[1], au[2], au[3],
                        ab + (uint32_t)(m * 16 * 128) + colA);
#pragma unroll
                for (int j = 0; j < 4; ++j) mma_tf32(acc[m][j], au, bu[j]);
            }
        }
        if (lane == 0) mbar_arrive(mbe + s * 8);

        // ---- tile boundary: tile0 epilogue + softmax (ALL warps, symmetric) ----
        if (kc == 15) {
#pragma unroll
            for (int m = 0; m < 4; ++m) {
#pragma unroll
                for (int rr = 0; rr < 2; ++rr) {
                    float pa = 0.f;
#pragma unroll
                    for (int j = 0; j < 4; ++j) {
#pragma unroll
                        for (int cc = 0; cc < 2; ++cc) {
                            int h = wc * 32 + j * 8 + t * 2 + cc;
                            pa += vas[h] * tanh_fast(qs[h] + acc[m][j][rr * 2 + cc]);
                        }
                    }
                    pa += __shfl_xor_sync(0xffffffffu, pa, 1);
                    pa += __shfl_xor_sync(0xffffffffu, pa, 2);
                    if (t == 0) es[wc * 128 + wr * 64 + m * 16 + rr * 8 + g] = pa;
#pragma unroll
                    for (int j = 0; j < 4; ++j)
#pragma unroll
                        for (int cc = 0; cc < 2; ++cc)
                            acc[m][j][rr * 2 + cc] = 0.f;
                }
            }
            __syncthreads();
            // softmax (energies bounded by sum|va| ~ 11: no max-pass)
            if (tid < 128) {
                float e = es[tid] + es[128 + tid] + es[256 + tid] + es[384 + tid];
                float p = __expf(e);
                ps0[tid] = p;
                g_p[rowA + tid] = p;
                float sZ = p;
#pragma unroll
                for (int o = 16; o > 0; o >>= 1) sZ += __shfl_xor_sync(0xffffffffu, sZ, o);
                if (lane == 0) red[warp] = sZ;
            }
            __syncthreads();   // ps0 + red visible to everyone
            if (tid == 0)
                g_pz[sx0] = red[0] + red[1] + red[2] + red[3];
        }

        // ---- chunks 16..31: one 8-row slice of tile0's context GEMV per iteration ----
        if (kc >= 16) {
            const int r0 = (kc - 16) * 8 + rh * 4;     // slice rows
            const float* Xp = X + (size_t)(rowA + r0) * QK + c4;
#pragma unroll
            for (int l = 0; l < 4; ++l) {
                float pl = ps0[r0 + l];
                float4 x = *reinterpret_cast<const float4*>(Xp + (size_t)l * QK);
                ctx0.x += pl * x.x; ctx0.y += pl * x.y;
                ctx0.z += pl * x.z; ctx0.w += pl * x.w;
            }
        }
    }

    // ---- tile1 epilogue (all warps) ----
#pragma unroll
    for (int m = 0; m < 4; ++m) {
#pragma unroll
        for (int rr = 0; rr < 2; ++rr) {
            float pa = 0.f;
#pragma unroll
            for (int j = 0; j < 4; ++j) {
#pragma unroll
                for (int cc = 0; cc < 2; ++cc) {
                    int h = wc * 32 + j * 8 + t * 2 + cc;
                    pa += vas[h] * tanh_fast(qs[h] + acc[m][j][rr * 2 + cc]);
                }
            }
            pa += __shfl_xor_sync(0xffffffffu, pa, 1);
            pa += __shfl_xor_sync(0xffffffffu, pa, 2);
            if (t == 0) es[wc * 128 + wr * 64 + m * 16 + rr * 8 + g] = pa;
        }
    }
    __syncthreads();

    const int rowB0 = rowA + 128;
    if (tid < 128) {
        float e = es[tid] + es[128 + tid] + es[256 + tid] + es[384 + tid];
        float p = __expf(e);
        ps1[tid] = p;
        g_p[rowB0 + tid] = p;
        float sZ = p;
#pragma unroll
        for (int o = 16; o > 0; o >>= 1) sZ += __shfl_xor_sync(0xffffffffu, sZ, o);
        if (lane == 0) red[warp] = sZ;
    }
    __syncthreads();
    if (tid == 0)
        g_pz[sx0 + 1] = red[0] + red[1] + red[2] + red[3];

    // ---- tile0 context combine (ctx0 regs -> g_pc[sx0]) ----
    if (rh == 1) *reinterpret_cast<float4*>(cst + c4) = ctx0;
    __syncthreads();
    if (rh == 0) {
        float4 b = *reinterpret_cast<const float4*>(cst + c4);
        ctx0.x += b.x; ctx0.y += b.y; ctx0.z += b.z; ctx0.w += b.w;
        *reinterpret_cast<float4*>(&g_pc[(size_t)sx0 * QK + c4]) = ctx0;
    }
    __syncthreads();   // cst free; ps1 visible

    // ---- tile1 context: 2 row-halves of 64, smem combine ----
    {
        const float* Xp = X + (size_t)(rowB0 + rh * 64) * QK + c4;
        float4 a0 = make_float4(0.f, 0.f, 0.f, 0.f);
        float4 a1 = make_float4(0.f, 0.f, 0.f, 0.f);
#pragma unroll 8
        for (int l = 0; l < 64; l += 2) {
            float pl0 = ps1[rh * 64 + l];
            float pl1 = ps1[rh * 64 + l + 1];
            float4 x0 = *reinterpret_cast<const float4*>(Xp + (size_t)l * QK);
            float4 x1 = *reinterpret_cast<const float4*>(Xp + (size_t)(l + 1) * QK);
            a0.x += pl0 * x0.x; a0.y += pl0 * x0.y; a0.z += pl0 * x0.z; a0.w += pl0 * x0.w;
            a1.x += pl1 * x1.x; a1.y += pl1 * x1.y; a1.z += pl1 * x1.z; a1.w += pl1 * x1.w;
        }
        a0.x += a1.x; a0.y += a1.y; a0.z += a1.z; a0.w += a1.w;
        if (rh == 1) *reinterpret_cast<float4*>(cst + c4) = a0;
        __syncthreads();
        if (rh == 0) {
            float4 b = *reinterpret_cast<const float4*>(cst + c4);
            a0.x += b.x; a0.y += b.y; a0.z += b.z; a0.w += b.w;
            *reinterpret_cast<float4*>(&g_pc[(size_t)(sx0 + 1) * QK + c4]) = a0;
        }
    }

    // ---- fan-in: both splits stored; +2 arrival; combine when batch complete ----
    __syncthreads();
    if (tid == 0) {
        __threadfence();
        int old = atomicAdd(&g_cnt[n], 2);
        s_last = (old == SPLITS - 2) ? 1 : 0;
    }
    __syncthreads();
    if (s_last) {
        __threadfence();
        float Z = 0.f;
#pragma unroll
        for (int i = 0; i < SPLITS; ++i) Z += g_pz[n * SPLITS + i];
        const float rZ = 1.f / Z;

        float* ctx = out;                       // (NB, QK)
        float* wts = out + (size_t)NB * QK;     // (NB, LL)
#pragma unroll
        for (int dd = 0; dd < QK / THREADS; ++dd) {
            int d = tid + dd * THREADS;
            float c = 0.f;
#pragma unroll
            for (int i = 0; i < SPLITS; ++i)
                c += g_pc[(size_t)(n * SPLITS + i) * QK + d];
            ctx[(size_t)n * QK + d] = c * rZ;
        }
#pragma unroll
        for (int i = 0; i < LL / THREADS; ++i) {
            int l = tid + i * THREADS;
            wts[(size_t)n * LL + l] = g_p[(size_t)n * LL + l] * rZ;
        }
        if (tid == 0) g_cnt[n] = 0;   // self-reset for next replay
    }
}

// ---------------- host: tensormap encode via runtime entry point (no -lcuda) ----------------
typedef CUresult (*tmap_encode_t)(
    CUtensorMap*, CUtensorMapDataType, cuuint32_t, void*,
    const cuuint64_t*, const cuuint64_t*, const cuuint32_t*, const cuuint32_t*,
    CUtensorMapInterleave, CUtensorMapSwizzle, CUtensorMapL2promotion, CUtensorMapFloatOOBfill);

extern "C" void kernel_launch(void* const* d_in, const int* in_sizes, int n_in,
                              void* d_out, int out_size) {
    const float* last_hidden     = (const float*)d_in[0];
    const float* encoder_outputs = (const float*)d_in[1];
    const float* Wa              = (const float*)d_in[2];
    const float* Ua              = (const float*)d_in[3];
    const float* va              = (const float*)d_in[4];
    float* out = (float*)d_out;

    static tmap_encode_t encode = nullptr;
    static bool attr_set = false;
    if (!attr_set) {
        cudaFuncSetAttribute(k_fused, cudaFuncAttributeMaxDynamicSharedMemorySize, SM_TOTAL);
        cudaDriverEntryPointQueryResult qr;
        void* fp = nullptr;
        cudaGetDriverEntryPoint("cuTensorMapEncodeTiled", &fp, cudaEnableDefault, &qr);
        encode = (tmap_encode_t)fp;
        attr_set = true;
    }

    CUtensorMap tmA, tmB;
    {   // X fp32: (NB*LL) x 512 floats; box 32x128, SW128
        cuuint64_t dims[2]   = {QK, (cuuint64_t)NB * LL};
        cuuint64_t stride[1] = {QK * sizeof(float)};
        cuuint32_t box[2]    = {32, TILE_ROWS};
        cuuint32_t elems[2]  = {1, 1};
        encode(&tmA, CU_TENSOR_MAP_DATA_TYPE_FLOAT32, 2, (void*)encoder_outputs,
               dims, stride, box, elems,
               CU_TENSOR_MAP_INTERLEAVE_NONE, CU_TENSOR_MAP_SWIZZLE_128B,
               CU_TENSOR_MAP_L2_PROMOTION_L2_128B, CU_TENSOR_MAP_FLOAT_OOB_FILL_NONE);
    }
    {   // Ua fp32: 128 x 512 floats; box 32x128, SW128
        cuuint64_t dims[2]   = {QK, HH};
        cuuint64_t stride[1] = {QK * sizeof(float)};
        cuuint32_t box[2]    = {32, HH};
        cuuint32_t elems[2]  = {1, 1};
        encode(&tmB, CU_TENSOR_MAP_DATA_TYPE_FLOAT32, 2, (void*)Ua,
               dims, stride, box, elems,
               CU_TENSOR_MAP_INTERLEAVE_NONE, CU_TENSOR_MAP_SWIZZLE_128B,
               CU_TENSOR_MAP_L2_PROMOTION_L2_128B, CU_TENSOR_MAP_FLOAT_OOB_FILL_NONE);
    }

    k_qproj<<<NB, 512>>>(last_hidden, Wa);
    k_fused<<<NCTAS, THREADS, SM_TOTAL>>>(tmA, tmB, encoder_outputs, va, out);
}

// round 15
// speedup vs baseline: 1.2063x; 1.2063x over previous
#include <cuda_runtime.h>
#include <cuda.h>
#include <cstdint>

// Problem dims (fixed)
#define NB   256
#define LL   2048
#define QK   512
#define HH   128

#define ROWS_PER_CTA 128
#define SPLITS       (LL / ROWS_PER_CTA)    // 16
#define NCTAS        (NB * SPLITS)          // 4096
#define KCHUNK       32                     // floats -> 128B rows (SW128 atom)
#define NCHUNKS      (QK / KCHUNK)          // 16
#define THREADS      256
#define NSTAGE       3

#define A_STAGE_BYTES 16384                 // 128 rows x 128B
#define B_STAGE_BYTES 16384                 // 128 rows x 128B
#define STAGE_TX      (A_STAGE_BYTES + B_STAGE_BYTES)

// smem byte offsets
#define SM_A     0
#define SM_B     (NSTAGE * A_STAGE_BYTES)              // 49152
#define SM_QS    (SM_B + NSTAGE * B_STAGE_BYTES)       // 98304
#define SM_VAS   (SM_QS + 512)                         // 98816
#define SM_ES4   (SM_VAS + 512)                        // 99328: 4 x 128 floats
#define SM_PS    (SM_ES4 + 2048)                       // 101376
#define SM_RED   (SM_PS + 512)                         // 101888
#define SM_CST   (SM_RED + 128)                        // 102016: 1 partial ctx slice
#define SM_MBAR  (SM_CST + 2048)                       // 104064: full[3] + empty[3]
#define SM_TOTAL (SM_MBAR + 64)                        // ~101.7 KB -> 2 CTAs/SM

// ---------------- device scratch ----------------
__device__ float g_q[NB * HH];              // q = Wa @ last_hidden
__device__ float g_p[NB * LL];
__device__ float g_pz[NCTAS];
__device__ float g_pc[(size_t)NCTAS * QK];
__device__ int   g_cnt[NB];                 // zero-init; self-resetting

// ---------------- helpers ----------------
__device__ __forceinline__ void mbar_init(uint32_t a, uint32_t cnt) {
    asm volatile("mbarrier.init.shared.b64 [%0], %1;" :: "r"(a), "r"(cnt) : "memory");
}
__device__ __forceinline__ void mbar_expect_tx(uint32_t a, uint32_t bytes) {
    asm volatile("mbarrier.arrive.expect_tx.shared.b64 _, [%0], %1;" :: "r"(a), "r"(bytes) : "memory");
}
__device__ __forceinline__ void mbar_arrive(uint32_t a) {
    asm volatile("mbarrier.arrive.shared.b64 _, [%0];" :: "r"(a) : "memory");
}
__device__ __forceinline__ void mbar_wait(uint32_t a, uint32_t par) {
    asm volatile(
        "{\n\t.reg .pred P1;\n"
        "WAIT_LOOP_%=:\n\t"
        "mbarrier.try_wait.parity.acquire.cta.shared::cta.b64 P1, [%0], %1, 0x989680;\n\t"
        "@P1 bra.uni WAIT_DONE_%=;\n\t"
        "bra.uni WAIT_LOOP_%=;\n"
        "WAIT_DONE_%=:\n\t}"
        :: "r"(a), "r"(par) : "memory");
}
__device__ __forceinline__ void tma2d(uint32_t dst, const CUtensorMap* m, int x, int y, uint32_t bar) {
    asm volatile(
        "cp.async.bulk.tensor.2d.shared::cta.global.tile.mbarrier::complete_tx::bytes "
        "[%0], [%1, {%2, %3}], [%4];"
        :: "r"(dst), "l"(m), "r"(x), "r"(y), "r"(bar) : "memory");
}
__device__ __forceinline__ void mma_tf32(float* c, const uint32_t* a, const uint32_t* b) {
    asm volatile(
        "mma.sync.aligned.m16n8k8.row.col.f32.tf32.tf32.f32 "
        "{%0,%1,%2,%3},{%4,%5,%6,%7},{%8,%9},{%0,%1,%2,%3};"
        : "+f"(c[0]), "+f"(c[1]), "+f"(c[2]), "+f"(c[3])
        : "r"(a[0]), "r"(a[1]), "r"(a[2]), "r"(a[3]), "r"(b[0]), "r"(b[1]));
}
__device__ __forceinline__ void ldsm_x4(uint32_t& r0, uint32_t& r1, uint32_t& r2, uint32_t& r3,
                                        uint32_t addr) {
    asm volatile("ldmatrix.sync.aligned.m8n8.x4.shared.b16 {%0,%1,%2,%3}, [%4];"
                 : "=r"(r0), "=r"(r1), "=r"(r2), "=r"(r3) : "r"(addr));
}
__device__ __forceinline__ float tanh_fast(float x) {
    float y; asm("tanh.approx.f32 %0, %1;" : "=f"(y) : "f"(x)); return y;
}

// ---------------- kernel 0: q projection (coalesced, warp-per-rows) ----------------
__global__ void __launch_bounds__(512)
k_qproj(const float* __restrict__ last_hidden, const float* __restrict__ Wa) {
    const int n    = blockIdx.x;
    const int warp = threadIdx.x >> 5;
    const int lane = threadIdx.x & 31;

    const float4* x4 = reinterpret_cast<const float4*>(last_hidden + (size_t)n * QK);
    float4 xv[4];
#pragma unroll
    for (int k = 0; k < 4; ++k) xv[k] = x4[lane + k * 32];

#pragma unroll
    for (int rr = 0; rr < 8; ++rr) {
        const int h = warp * 8 + rr;
        const float4* w4 = reinterpret_cast<const float4*>(Wa + (size_t)h * QK);
        float a = 0.f;
#pragma unroll
        for (int k = 0; k < 4; ++k) {
            float4 w = w4[lane + k * 32];
            a += w.x * xv[k].x + w.y * xv[k].y + w.z * xv[k].z + w.w * xv[k].w;
        }
#pragma unroll
        for (int o = 16; o > 0; o >>= 1) a += __shfl_xor_sync(0xffffffffu, a, o);
        if (lane == 0) g_q[n * HH + h] = a;
    }
}

// ---------------- kernel 1: TMA-fed, full/empty-mbarrier fused kernel ----------------
__global__ void __launch_bounds__(THREADS, 2)
k_fused(const __grid_constant__ CUtensorMap tmA,   // X tiles, SW128
        const __grid_constant__ CUtensorMap tmB,   // Ua tiles, SW128
        const float* __restrict__ X,               // (NB,LL,QK) for context re-read
        const float* __restrict__ va,              // (1,HH)
        float* __restrict__ out) {
    extern __shared__ __align__(1024) char sm[];
    const uint32_t su = (uint32_t)__cvta_generic_to_shared(sm);
    float* qs  = reinterpret_cast<float*>(sm + SM_QS);
    float* vas = reinterpret_cast<float*>(sm + SM_VAS);
    float* es4 = reinterpret_cast<float*>(sm + SM_ES4);
    float* ps  = reinterpret_cast<float*>(sm + SM_PS);
    float* red = reinterpret_cast<float*>(sm + SM_RED);
    float* cst = reinterpret_cast<float*>(sm + SM_CST);
    __shared__ int s_last;

    const int tid  = threadIdx.x;
    const int bx   = blockIdx.x;
    const int row0 = bx * ROWS_PER_CTA;
    const int n    = row0 >> 11;              // row0 / 2048

    const int warp = tid >> 5;
    const int lane = tid & 31;
    const int wr = warp >> 2;          // 0..1 : 64-row strip
    const int wc = warp & 3;           // 0..3 : 32-col strip
    const int g  = lane >> 2;
    const int t  = lane & 3;

    // ldmatrix per-lane addressing (16B segments, SW128-swizzled rows)
    const int swz  = (lane & 7) << 4;
    const int rowA = lane & 15;
    const int hiA  = (lane >> 4) << 4;
    const int rowB = (lane & 7) + ((lane >> 4) << 3);
    const int hiB  = ((lane >> 3) & 1) << 4;

    const uint32_t mbf = su + SM_MBAR;        // full[s] at +s*8
    const uint32_t mbe = su + SM_MBAR + 24;   // empty[s] at +s*8

    if (tid == 0) {
#pragma unroll
        for (int s = 0; s < NSTAGE; ++s) {
            mbar_init(mbf + s * 8, 1);     // flipped by expect_tx + TMA complete
            mbar_init(mbe + s * 8, 8);     // flipped by 8 warp arrivals
        }
    }
    if (tid < HH) {
        vas[tid] = va[tid];
        qs[tid]  = g_q[n * HH + tid];
    }
    __syncthreads();   // mbarrier init + qs visible

    // prologue: fill all 3 stages (buffers empty at start -> no empty-wait)
    if (tid == 0) {
#pragma unroll
        for (int c = 0; c < NSTAGE; ++c) {
            mbar_expect_tx(mbf + c * 8, STAGE_TX);
            tma2d(su + SM_A + c * A_STAGE_BYTES, &tmA, c * KCHUNK, row0, mbf + c * 8);
            tma2d(su + SM_B + c * B_STAGE_BYTES, &tmB, c * KCHUNK, 0, mbf + c * 8);
        }
    }

    float acc[4][4][4];
#pragma unroll
    for (int m = 0; m < 4; ++m)
#pragma unroll
        for (int j = 0; j < 4; ++j)
#pragma unroll
            for (int c = 0; c < 4; ++c) acc[m][j][c] = 0.f;

    const uint32_t a_tile_off = (uint32_t)((wr * 64 + rowA) * 128);
    const uint32_t b_tile_off = (uint32_t)((wc * 32 + rowB) * 128);

    // ---- mainloop: no block-wide sync; per-warp full/empty protocol ----
#pragma unroll 1
    for (int kc = 0; kc < NCHUNKS; ++kc) {
        const int s = kc - (kc / NSTAGE) * NSTAGE;      // kc % 3
        const int phase = (kc / NSTAGE) & 1;

        // producer: issue chunk kc+2 into its stage after that stage drains
        // (chunks 0..2 already issued by prologue -> start at kc=1)
        if (tid == 0 && kc >= 1 && kc + 2 < NCHUNKS) {
            const int c  = kc + 2;
            int ns = c - (c / NSTAGE) * NSTAGE;
            mbar_wait(mbe + ns * 8, (uint32_t)(((c - NSTAGE) / NSTAGE) & 1));
            mbar_expect_tx(mbf + ns * 8, STAGE_TX);
            tma2d(su + SM_A + ns * A_STAGE_BYTES, &tmA, c * KCHUNK, row0, mbf + ns * 8);
            tma2d(su + SM_B + ns * B_STAGE_BYTES, &tmB, c * KCHUNK, 0, mbf + ns * 8);
        }

        mbar_wait(mbf + s * 8, (uint32_t)phase);        // chunk kc resident

        const uint32_t abase = su + SM_A + s * A_STAGE_BYTES + a_tile_off;
        const uint32_t bbase = su + SM_B + s * B_STAGE_BYTES + b_tile_off;

#pragma unroll
        for (int ks = 0; ks < 4; ++ks) {
            const uint32_t colA = (uint32_t)((ks * 32 + hiA) ^ swz);
            const uint32_t colB = (uint32_t)((ks * 32 + hiB) ^ swz);

            uint32_t bu[4][2];
#pragma unroll
            for (int jj = 0; jj < 2; ++jj) {
                ldsm_x4(bu[2*jj][0], bu[2*jj][1], bu[2*jj+1][0], bu[2*jj+1][1],
                        bbase + (uint32_t)(jj * 16 * 128) + colB);
            }
#pragma unroll
            for (int m = 0; m < 4; ++m) {
                uint32_t au[4];
                ldsm_x4(au[0], au[1], au[2], au[3],
                        abase + (uint32_t)(m * 16 * 128) + colA);
#pragma unroll
                for (int j = 0; j < 4; ++j) mma_tf32(acc[m][j], au, bu[j]);
            }
        }
        if (lane == 0) mbar_arrive(mbe + s * 8);        // this warp done with stage s
    }

    // ---- epilogue: e_r = sum_h va[h] * tanh(q[h] + C[r,h]) ; per-wc partials ----
#pragma unroll
    for (int m = 0; m < 4; ++m) {
#pragma unroll
        for (int rr = 0; rr < 2; ++rr) {
            float pa = 0.f;
#pragma unroll
            for (int j = 0; j < 4; ++j) {
#pragma unroll
                for (int cc = 0; cc < 2; ++cc) {
                    int h = wc * 32 + j * 8 + t * 2 + cc;
                    pa += vas[h] * tanh_fast(qs[h] + acc[m][j][rr * 2 + cc]);
                }
            }
            pa += __shfl_xor_sync(0xffffffffu, pa, 1);
            pa += __shfl_xor_sync(0xffffffffu, pa, 2);
            if (t == 0) es4[wc * 128 + wr * 64 + m * 16 + rr * 8 + g] = pa;
        }
    }
    __syncthreads();

    // energies bounded (|e| <= sum|va| ~= 11): exp without max-pass is safe
    if (tid < ROWS_PER_CTA) {
        float e = es4[tid] + es4[128 + tid] + es4[256 + tid] + es4[384 + tid];
        float p = __expf(e);
        ps[tid] = p;
        g_p[row0 + tid] = p;
        float s = p;
#pragma unroll
        for (int o = 16; o > 0; o >>= 1) s += __shfl_xor_sync(0xffffffffu, s, o);
        if (lane == 0) red[warp] = s;
    }
    __syncthreads();
    if (tid == 0) {
        float Z = 0.f;
#pragma unroll
        for (int i = 0; i < 4; ++i) Z += red[i];
        g_pz[bx] = Z;
    }
    __syncthreads();   // ps[] visible

    // ---- partial context: 2 row-halves of 64, then smem combine ----
    {
        const int c4 = (tid & 127) * 4;
        const int half = tid >> 7;               // 0 or 1
        const float* Xp = X + (size_t)(row0 + half * 64) * QK + c4;
        float4 a = make_float4(0.f, 0.f, 0.f, 0.f);
#pragma unroll 8
        for (int l = 0; l < 64; ++l) {
            float pl = ps[half * 64 + l];
            float4 x = *reinterpret_cast<const float4*>(Xp + (size_t)l * QK);
            a.x += pl * x.x; a.y += pl * x.y; a.z += pl * x.z; a.w += pl * x.w;
        }
        if (half == 1) *reinterpret_cast<float4*>(cst + c4) = a;
        __syncthreads();
        if (half == 0) {
            float4 b = *reinterpret_cast<const float4*>(cst + c4);
            a.x += b.x; a.y += b.y; a.z += b.z; a.w += b.w;
            *reinterpret_cast<float4*>(&g_pc[(size_t)bx * QK + c4]) = a;
        }
    }

    // ---- fan-in: last CTA of the batch combines ----
    __syncthreads();
    if (tid == 0) {
        __threadfence();
        int old = atomicAdd(&g_cnt[n], 1);
        s_last = (old == SPLITS - 1) ? 1 : 0;
    }
    __syncthreads();
    if (s_last) {
        __threadfence();
        float Z = 0.f;
#pragma unroll
        for (int i = 0; i < SPLITS; ++i) Z += g_pz[n * SPLITS + i];
        const float rZ = 1.f / Z;

        float* ctx = out;                       // (NB, QK)
        float* wts = out + (size_t)NB * QK;     // (NB, LL)
        // context combine: float4, 256 threads cover 512 cols -> each does one float4 at 2x stride
        {
            int d4 = (tid & 127) * 4 + (tid >> 7) * 512;   // two half-warpsets cover [0,512)
            // (tid>>7)*512 exceeds QK for half threads; remap: tid 0..127 -> cols 0..511 via 4-float
            // simpler: 128 float4 slots, threads 0..127 handle them; threads 128..255 handle weights head start
            if (tid < 128) {
                float4 c = make_float4(0.f, 0.f, 0.f, 0.f);
#pragma unroll
                for (int i = 0; i < SPLITS; ++i) {
                    float4 v = *reinterpret_cast<const float4*>(
                        &g_pc[(size_t)(n * SPLITS + i) * QK + tid * 4]);
                    c.x += v.x; c.y += v.y; c.z += v.z; c.w += v.w;
                }
                c.x *= rZ; c.y *= rZ; c.z *= rZ; c.w *= rZ;
                *reinterpret_cast<float4*>(&ctx[(size_t)n * QK + tid * 4]) = c;
            }
            (void)d4;
        }
        // weights: float4 over 2048 cols = 512 float4 slots / 256 threads
#pragma unroll
        for (int i = 0; i < 2; ++i) {
            int l4 = tid + i * THREADS;          // 0..511
            float4 p4 = *reinterpret_cast<const float4*>(&g_p[(size_t)n * LL + l4 * 4]);
            p4.x *= rZ; p4.y *= rZ; p4.z *= rZ; p4.w *= rZ;
            *reinterpret_cast<float4*>(&wts[(size_t)n * LL + l4 * 4]) = p4;
        }
        if (tid == 0) g_cnt[n] = 0;   // self-reset for next replay
    }
}

// ---------------- host: tensormap encode via runtime entry point (no -lcuda) ----------------
typedef CUresult (*tmap_encode_t)(
    CUtensorMap*, CUtensorMapDataType, cuuint32_t, void*,
    const cuuint64_t*, const cuuint64_t*, const cuuint32_t*, const cuuint32_t*,
    CUtensorMapInterleave, CUtensorMapSwizzle, CUtensorMapL2promotion, CUtensorMapFloatOOBfill);

extern "C" void kernel_launch(void* const* d_in, const int* in_sizes, int n_in,
                              void* d_out, int out_size) {
    const float* last_hidden     = (const float*)d_in[0];
    const float* encoder_outputs = (const float*)d_in[1];
    const float* Wa              = (const float*)d_in[2];
    const float* Ua              = (const float*)d_in[3];
    const float* va              = (const float*)d_in[4];
    float* out = (float*)d_out;

    static tmap_encode_t encode = nullptr;
    static bool attr_set = false;
    if (!attr_set) {
        cudaFuncSetAttribute(k_fused, cudaFuncAttributeMaxDynamicSharedMemorySize, SM_TOTAL);
        cudaDriverEntryPointQueryResult qr;
        void* fp = nullptr;
        cudaGetDriverEntryPoint("cuTensorMapEncodeTiled", &fp, cudaEnableDefault, &qr);
        encode = (tmap_encode_t)fp;
        attr_set = true;
    }

    CUtensorMap tmA, tmB;
    {
        cuuint64_t dims[2]   = {QK, (cuuint64_t)NB * LL};
        cuuint64_t stride[1] = {QK * sizeof(float)};
        cuuint32_t box[2]    = {KCHUNK, ROWS_PER_CTA};
        cuuint32_t elems[2]  = {1, 1};
        encode(&tmA, CU_TENSOR_MAP_DATA_TYPE_FLOAT32, 2, (void*)encoder_outputs,
               dims, stride, box, elems,
               CU_TENSOR_MAP_INTERLEAVE_NONE, CU_TENSOR_MAP_SWIZZLE_128B,
               CU_TENSOR_MAP_L2_PROMOTION_L2_128B, CU_TENSOR_MAP_FLOAT_OOB_FILL_NONE);
    }
    {
        cuuint64_t dims[2]   = {QK, HH};
        cuuint64_t stride[1] = {QK * sizeof(float)};
        cuuint32_t box[2]    = {KCHUNK, HH};
        cuuint32_t elems[2]  = {1, 1};
        encode(&tmB, CU_TENSOR_MAP_DATA_TYPE_FLOAT32, 2, (void*)Ua,
               dims, stride, box, elems,
               CU_TENSOR_MAP_INTERLEAVE_NONE, CU_TENSOR_MAP_SWIZZLE_128B,
               CU_TENSOR_MAP_L2_PROMOTION_L2_128B, CU_TENSOR_MAP_FLOAT_OOB_FILL_NONE);
    }

    k_qproj<<<NB, 512>>>(last_hidden, Wa);
    k_fused<<<NCTAS, THREADS, SM_TOTAL>>>(tmA, tmB, encoder_outputs, va, out);
}

// round 16
// speedup vs baseline: 1.2826x; 1.0633x over previous
#include <cuda_runtime.h>
#include <cuda.h>
#include <cstdint>

// Problem dims (fixed)
#define NB   256
#define LL   2048
#define QK   512
#define HH   128

#define ROWS_PER_CTA 128
#define SPLITS       (LL / ROWS_PER_CTA)    // 16
#define NCTAS        (NB * SPLITS)          // 4096
#define KCHUNK       32                     // floats -> 128B rows (SW128 atom)
#define NCHUNKS      (QK / KCHUNK)          // 16
#define THREADS      256
#define NSTAGE       3

#define A_STAGE_BYTES 16384                 // 128 rows x 128B
#define B_STAGE_BYTES 16384                 // 128 rows x 128B
#define STAGE_TX      (A_STAGE_BYTES + B_STAGE_BYTES)

// smem byte offsets
#define SM_A     0
#define SM_B     (NSTAGE * A_STAGE_BYTES)              // 49152
#define SM_QS    (SM_B + NSTAGE * B_STAGE_BYTES)       // 98304
#define SM_VAS   (SM_QS + 512)                         // 98816
#define SM_ES4   (SM_VAS + 512)                        // 99328: 4 x 128 floats
#define SM_PS    (SM_ES4 + 2048)                       // 101376
#define SM_RED   (SM_PS + 512)                         // 101888
#define SM_CST   (SM_RED + 128)                        // 102016: 1 partial ctx slice
#define SM_MBAR  (SM_CST + 2048)                       // 104064: full[3] + empty[3]
#define SM_TOTAL (SM_MBAR + 64)                        // ~101.7 KB -> 2 CTAs/SM

// ---------------- device scratch ----------------
__device__ float g_q[NB * HH];              // q = Wa @ last_hidden
__device__ float g_p[NB * LL];
__device__ float g_pz[NCTAS];
__device__ float g_pc[(size_t)NCTAS * QK];
__device__ int   g_cnt[NB];                 // zero-init; self-resetting

// ---------------- helpers ----------------
__device__ __forceinline__ void mbar_init(uint32_t a, uint32_t cnt) {
    asm volatile("mbarrier.init.shared.b64 [%0], %1;" :: "r"(a), "r"(cnt) : "memory");
}
__device__ __forceinline__ void mbar_expect_tx(uint32_t a, uint32_t bytes) {
    asm volatile("mbarrier.arrive.expect_tx.shared.b64 _, [%0], %1;" :: "r"(a), "r"(bytes) : "memory");
}
__device__ __forceinline__ void mbar_arrive(uint32_t a) {
    asm volatile("mbarrier.arrive.shared.b64 _, [%0];" :: "r"(a) : "memory");
}
__device__ __forceinline__ void mbar_wait(uint32_t a, uint32_t par) {
    asm volatile(
        "{\n\t.reg .pred P1;\n"
        "WAIT_LOOP_%=:\n\t"
        "mbarrier.try_wait.parity.acquire.cta.shared::cta.b64 P1, [%0], %1, 0x989680;\n\t"
        "@P1 bra.uni WAIT_DONE_%=;\n\t"
        "bra.uni WAIT_LOOP_%=;\n"
        "WAIT_DONE_%=:\n\t}"
        :: "r"(a), "r"(par) : "memory");
}
__device__ __forceinline__ void tma2d(uint32_t dst, const CUtensorMap* m, int x, int y, uint32_t bar) {
    asm volatile(
        "cp.async.bulk.tensor.2d.shared::cta.global.tile.mbarrier::complete_tx::bytes "
        "[%0], [%1, {%2, %3}], [%4];"
        :: "r"(dst), "l"(m), "r"(x), "r"(y), "r"(bar) : "memory");
}
__device__ __forceinline__ void mma_tf32(float* c, const uint32_t* a, const uint32_t* b) {
    asm volatile(
        "mma.sync.aligned.m16n8k8.row.col.f32.tf32.tf32.f32 "
        "{%0,%1,%2,%3},{%4,%5,%6,%7},{%8,%9},{%0,%1,%2,%3};"
        : "+f"(c[0]), "+f"(c[1]), "+f"(c[2]), "+f"(c[3])
        : "r"(a[0]), "r"(a[1]), "r"(a[2]), "r"(a[3]), "r"(b[0]), "r"(b[1]));
}
__device__ __forceinline__ void ldsm_x4(uint32_t& r0, uint32_t& r1, uint32_t& r2, uint32_t& r3,
                                        uint32_t addr) {
    asm volatile("ldmatrix.sync.aligned.m8n8.x4.shared.b16 {%0,%1,%2,%3}, [%4];"
                 : "=r"(r0), "=r"(r1), "=r"(r2), "=r"(r3) : "r"(addr));
}
__device__ __forceinline__ float tanh_fast(float x) {
    float y; asm("tanh.approx.f32 %0, %1;" : "=f"(y) : "f"(x)); return y;
}

// ---------------- kernel 0: q projection (coalesced, warp-per-rows) ----------------
__global__ void __launch_bounds__(512)
k_qproj(const float* __restrict__ last_hidden, const float* __restrict__ Wa) {
    const int n    = blockIdx.x;
    const int warp = threadIdx.x >> 5;
    const int lane = threadIdx.x & 31;

    const float4* x4 = reinterpret_cast<const float4*>(last_hidden + (size_t)n * QK);
    float4 xv[4];
#pragma unroll
    for (int k = 0; k < 4; ++k) xv[k] = x4[lane + k * 32];

#pragma unroll
    for (int rr = 0; rr < 8; ++rr) {
        const int h = warp * 8 + rr;
        const float4* w4 = reinterpret_cast<const float4*>(Wa + (size_t)h * QK);
        float a = 0.f;
#pragma unroll
        for (int k = 0; k < 4; ++k) {
            float4 w = w4[lane + k * 32];
            a += w.x * xv[k].x + w.y * xv[k].y + w.z * xv[k].z + w.w * xv[k].w;
        }
#pragma unroll
        for (int o = 16; o > 0; o >>= 1) a += __shfl_xor_sync(0xffffffffu, a, o);
        if (lane == 0) g_q[n * HH + h] = a;
    }
}

// ---------------- kernel 1: TMA-fed, full/empty-mbarrier fused kernel ----------------
__global__ void __launch_bounds__(THREADS, 2)
k_fused(const __grid_constant__ CUtensorMap tmA,   // X tiles, SW128
        const __grid_constant__ CUtensorMap tmB,   // Ua tiles, SW128
        const float* __restrict__ X,               // (NB,LL,QK) for context re-read
        const float* __restrict__ va,              // (1,HH)
        float* __restrict__ out) {
    extern __shared__ __align__(1024) char sm[];
    const uint32_t su = (uint32_t)__cvta_generic_to_shared(sm);
    float* qs  = reinterpret_cast<float*>(sm + SM_QS);
    float* vas = reinterpret_cast<float*>(sm + SM_VAS);
    float* es4 = reinterpret_cast<float*>(sm + SM_ES4);
    float* ps  = reinterpret_cast<float*>(sm + SM_PS);
    float* red = reinterpret_cast<float*>(sm + SM_RED);
    float* cst = reinterpret_cast<float*>(sm + SM_CST);
    __shared__ int s_last;

    const int tid  = threadIdx.x;
    const int bx   = blockIdx.x;
    const int row0 = bx * ROWS_PER_CTA;
    const int n    = row0 >> 11;              // row0 / 2048

    const int warp = tid >> 5;
    const int lane = tid & 31;
    const int wr = warp >> 2;          // 0..1 : 64-row strip
    const int wc = warp & 3;           // 0..3 : 32-col strip
    const int g  = lane >> 2;
    const int t  = lane & 3;

    // ldmatrix per-lane addressing (16B segments, SW128-swizzled rows)
    const int swz  = (lane & 7) << 4;
    const int rowA = lane & 15;
    const int hiA  = (lane >> 4) << 4;
    const int rowB = (lane & 7) + ((lane >> 4) << 3);
    const int hiB  = ((lane >> 3) & 1) << 4;

    const uint32_t mbf = su + SM_MBAR;        // full[s] at +s*8
    const uint32_t mbe = su + SM_MBAR + 24;   // empty[s] at +s*8

    if (tid == 0) {
#pragma unroll
        for (int s = 0; s < NSTAGE; ++s) {
            mbar_init(mbf + s * 8, 1);     // flipped by expect_tx + TMA complete
            mbar_init(mbe + s * 8, 8);     // flipped by 8 warp arrivals
        }
    }
    if (tid < HH) {
        vas[tid] = va[tid];
        qs[tid]  = g_q[n * HH + tid];
    }
    __syncthreads();   // mbarrier init + qs visible

    // prologue: fill all 3 stages (buffers empty at start -> no empty-wait)
    if (tid == 0) {
#pragma unroll
        for (int c = 0; c < NSTAGE; ++c) {
            mbar_expect_tx(mbf + c * 8, STAGE_TX);
            tma2d(su + SM_A + c * A_STAGE_BYTES, &tmA, c * KCHUNK, row0, mbf + c * 8);
            tma2d(su + SM_B + c * B_STAGE_BYTES, &tmB, c * KCHUNK, 0, mbf + c * 8);
        }
    }

    float acc[4][4][4];
#pragma unroll
    for (int m = 0; m < 4; ++m)
#pragma unroll
        for (int j = 0; j < 4; ++j)
#pragma unroll
            for (int c = 0; c < 4; ++c) acc[m][j][c] = 0.f;

    // stage-constant tile bases (hoisted; stage index folded at compile time below)
    const uint32_t aBase0 = su + SM_A + (uint32_t)((wr * 64 + rowA) * 128);
    const uint32_t bBase0 = su + SM_B + (uint32_t)((wc * 32 + rowB) * 128);

    // one chunk of work; s is a compile-time literal at every call site
    auto do_chunk = [&](int kc, const int s, uint32_t phase) __attribute__((always_inline)) {
        // producer: issue chunk kc+2 into stage (s+2)%3 after that stage drains
        if (tid == 0 && kc >= 1 && kc + 2 < NCHUNKS) {
            const int c  = kc + 2;
            const int ns = (s + 2 >= NSTAGE) ? (s - 1) : (s + 2);   // folds to literal
            mbar_wait(mbe + ns * 8, (uint32_t)(((c - NSTAGE) / NSTAGE) & 1));
            mbar_expect_tx(mbf + ns * 8, STAGE_TX);
            tma2d(su + SM_A + ns * A_STAGE_BYTES, &tmA, c * KCHUNK, row0, mbf + ns * 8);
            tma2d(su + SM_B + ns * B_STAGE_BYTES, &tmB, c * KCHUNK, 0, mbf + ns * 8);
        }

        mbar_wait(mbf + s * 8, phase);        // chunk kc resident

        const uint32_t abase = aBase0 + (uint32_t)(s * A_STAGE_BYTES);
        const uint32_t bbase = bBase0 + (uint32_t)(s * B_STAGE_BYTES);

#pragma unroll
        for (int ks = 0; ks < 4; ++ks) {
            const uint32_t colA = (uint32_t)((ks * 32 + hiA) ^ swz);
            const uint32_t colB = (uint32_t)((ks * 32 + hiB) ^ swz);

            uint32_t bu[4][2];
#pragma unroll
            for (int jj = 0; jj < 2; ++jj) {
                ldsm_x4(bu[2*jj][0], bu[2*jj][1], bu[2*jj+1][0], bu[2*jj+1][1],
                        bbase + (uint32_t)(jj * 16 * 128) + colB);
            }
#pragma unroll
            for (int m = 0; m < 4; ++m) {
                uint32_t au[4];
                ldsm_x4(au[0], au[1], au[2], au[3],
                        abase + (uint32_t)(m * 16 * 128) + colA);
#pragma unroll
                for (int j = 0; j < 4; ++j) mma_tf32(acc[m][j], au, bu[j]);
            }
        }
        if (lane == 0) mbar_arrive(mbe + s * 8);        // this warp done with stage s
    };

    // ---- mainloop: 5 unrolled stage-triples + final chunk (stage literals) ----
#pragma unroll 1
    for (int kp = 0; kp < 15; kp += 3) {
        const uint32_t ph = (uint32_t)((kp / 3) & 1);
        do_chunk(kp + 0, 0, ph);
        do_chunk(kp + 1, 1, ph);
        do_chunk(kp + 2, 2, ph);
    }
    do_chunk(15, 0, 1u);   // kc=15: stage 0, phase (15/3)&1 = 1

    // ---- epilogue: e_r = sum_h va[h] * tanh(q[h] + C[r,h]) ; per-wc partials ----
#pragma unroll
    for (int m = 0; m < 4; ++m) {
#pragma unroll
        for (int rr = 0; rr < 2; ++rr) {
            float pa = 0.f;
#pragma unroll
            for (int j = 0; j < 4; ++j) {
#pragma unroll
                for (int cc = 0; cc < 2; ++cc) {
                    int h = wc * 32 + j * 8 + t * 2 + cc;
                    pa += vas[h] * tanh_fast(qs[h] + acc[m][j][rr * 2 + cc]);
                }
            }
            pa += __shfl_xor_sync(0xffffffffu, pa, 1);
            pa += __shfl_xor_sync(0xffffffffu, pa, 2);
            if (t == 0) es4[wc * 128 + wr * 64 + m * 16 + rr * 8 + g] = pa;
        }
    }
    __syncthreads();

    // energies bounded (|e| <= sum|va| ~= 11): exp without max-pass is safe
    if (tid < ROWS_PER_CTA) {
        float e = es4[tid] + es4[128 + tid] + es4[256 + tid] + es4[384 + tid];
        float p = __expf(e);
        ps[tid] = p;
        g_p[row0 + tid] = p;
        float s = p;
#pragma unroll
        for (int o = 16; o > 0; o >>= 1) s += __shfl_xor_sync(0xffffffffu, s, o);
        if (lane == 0) red[warp] = s;
    }
    __syncthreads();
    if (tid == 0) {
        float Z = 0.f;
#pragma unroll
        for (int i = 0; i < 4; ++i) Z += red[i];
        g_pz[bx] = Z;
    }
    __syncthreads();   // ps[] visible

    // ---- partial context: 2 row-halves of 64, then smem combine ----
    {
        const int c4 = (tid & 127) * 4;
        const int half = tid >> 7;               // 0 or 1
        const float* Xp = X + (size_t)(row0 + half * 64) * QK + c4;
        float4 a = make_float4(0.f, 0.f, 0.f, 0.f);
#pragma unroll 8
        for (int l = 0; l < 64; ++l) {
            float pl = ps[half * 64 + l];
            float4 x = *reinterpret_cast<const float4*>(Xp + (size_t)l * QK);
            a.x += pl * x.x; a.y += pl * x.y; a.z += pl * x.z; a.w += pl * x.w;
        }
        if (half == 1) *reinterpret_cast<float4*>(cst + c4) = a;
        __syncthreads();
        if (half == 0) {
            float4 b = *reinterpret_cast<const float4*>(cst + c4);
            a.x += b.x; a.y += b.y; a.z += b.z; a.w += b.w;
            *reinterpret_cast<float4*>(&g_pc[(size_t)bx * QK + c4]) = a;
        }
    }

    // ---- fan-in: last CTA of the batch combines ----
    __syncthreads();
    if (tid == 0) {
        __threadfence();
        int old = atomicAdd(&g_cnt[n], 1);
        s_last = (old == SPLITS - 1) ? 1 : 0;
    }
    __syncthreads();
    if (s_last) {
        __threadfence();
        float Z = 0.f;
#pragma unroll
        for (int i = 0; i < SPLITS; ++i) Z += g_pz[n * SPLITS + i];
        const float rZ = 1.f / Z;

        float* ctx = out;                       // (NB, QK)
        float* wts = out + (size_t)NB * QK;     // (NB, LL)
        if (tid < 128) {                        // 128 float4 slots cover QK=512
            float4 c = make_float4(0.f, 0.f, 0.f, 0.f);
#pragma unroll
            for (int i = 0; i < SPLITS; ++i) {
                float4 v = *reinterpret_cast<const float4*>(
                    &g_pc[(size_t)(n * SPLITS + i) * QK + tid * 4]);
                c.x += v.x; c.y += v.y; c.z += v.z; c.w += v.w;
            }
            c.x *= rZ; c.y *= rZ; c.z *= rZ; c.w *= rZ;
            *reinterpret_cast<float4*>(&ctx[(size_t)n * QK + tid * 4]) = c;
        }
#pragma unroll
        for (int i = 0; i < 2; ++i) {           // 512 float4 slots cover LL=2048
            int l4 = tid + i * THREADS;
            float4 p4 = *reinterpret_cast<const float4*>(&g_p[(size_t)n * LL + l4 * 4]);
            p4.x *= rZ; p4.y *= rZ; p4.z *= rZ; p4.w *= rZ;
            *reinterpret_cast<float4*>(&wts[(size_t)n * LL + l4 * 4]) = p4;
        }
        if (tid == 0) g_cnt[n] = 0;   // self-reset for next replay
    }
}

// ---------------- host: tensormap encode via runtime entry point (no -lcuda) ----------------
typedef CUresult (*tmap_encode_t)(
    CUtensorMap*, CUtensorMapDataType, cuuint32_t, void*,
    const cuuint64_t*, const cuuint64_t*, const cuuint32_t*, const cuuint32_t*,
    CUtensorMapInterleave, CUtensorMapSwizzle, CUtensorMapL2promotion, CUtensorMapFloatOOBfill);

extern "C" void kernel_launch(void* const* d_in, const int* in_sizes, int n_in,
                              void* d_out, int out_size) {
    const float* last_hidden     = (const float*)d_in[0];
    const float* encoder_outputs = (const float*)d_in[1];
    const float* Wa              = (const float*)d_in[2];
    const float* Ua              = (const float*)d_in[3];
    const float* va              = (const float*)d_in[4];
    float* out = (float*)d_out;

    static tmap_encode_t encode = nullptr;
    static bool attr_set = false;
    if (!attr_set) {
        cudaFuncSetAttribute(k_fused, cudaFuncAttributeMaxDynamicSharedMemorySize, SM_TOTAL);
        cudaDriverEntryPointQueryResult qr;
        void* fp = nullptr;
        cudaGetDriverEntryPoint("cuTensorMapEncodeTiled", &fp, cudaEnableDefault, &qr);
        encode = (tmap_encode_t)fp;
        attr_set = true;
    }

    CUtensorMap tmA, tmB;
    {
        cuuint64_t dims[2]   = {QK, (cuuint64_t)NB * LL};
        cuuint64_t stride[1] = {QK * sizeof(float)};
        cuuint32_t box[2]    = {KCHUNK, ROWS_PER_CTA};
        cuuint32_t elems[2]  = {1, 1};
        encode(&tmA, CU_TENSOR_MAP_DATA_TYPE_FLOAT32, 2, (void*)encoder_outputs,
               dims, stride, box, elems,
               CU_TENSOR_MAP_INTERLEAVE_NONE, CU_TENSOR_MAP_SWIZZLE_128B,
               CU_TENSOR_MAP_L2_PROMOTION_L2_128B, CU_TENSOR_MAP_FLOAT_OOB_FILL_NONE);
    }
    {
        cuuint64_t dims[2]   = {QK, HH};
        cuuint64_t stride[1] = {QK * sizeof(float)};
        cuuint32_t box[2]    = {KCHUNK, HH};
        cuuint32_t elems[2]  = {1, 1};
        encode(&tmB, CU_TENSOR_MAP_DATA_TYPE_FLOAT32, 2, (void*)Ua,
               dims, stride, box, elems,
               CU_TENSOR_MAP_INTERLEAVE_NONE, CU_TENSOR_MAP_SWIZZLE_128B,
               CU_TENSOR_MAP_L2_PROMOTION_L2_128B, CU_TENSOR_MAP_FLOAT_OOB_FILL_NONE);
    }

    k_qproj<<<NB, 512>>>(last_hidden, Wa);
    k_fused<<<NCTAS, THREADS, SM_TOTAL>>>(tmA, tmB, encoder_outputs, va, out);
}